// round 15
// baseline (speedup 1.0000x reference)
#include <cuda_runtime.h>
#include <cstdint>

#define B_SZ   8192
#define IN_SZ  2048
#define OUT_SZ 2048
#define G_SZ   5
#define KPACK  6
#define K_SZ   (IN_SZ * KPACK)   // 12288
#define EPS_F  1e-8f

#define BM 256
#define BN 128
#define BK 64
#define KSPLIT 2
#define KITERS_H (K_SZ / BK / KSPLIT)   // 96 per k-slice
#define NSTAGE 2
#define A_STAGE_BYTES (16 * 8 * 512)    // 64 KB
#define B_STAGE_BYTES (16 * 4 * 512)    // 32 KB
#define STAGE_BYTES (A_STAGE_BYTES + B_STAGE_BYTES)   // 96 KB

#define NKG   (K_SZ / 8)          // 1536 k-groups (A)
#define NKGP  (K_SZ / 16)         // 768 kgroup-pairs (B)
#define CELEMS ((size_t)B_SZ * OUT_SZ)

__device__ __align__(128) float g_Apack[(size_t)B_SZ  * K_SZ];
__device__ __align__(128) float g_Wpack[(size_t)OUT_SZ * K_SZ];
__device__ __align__(128) float g_part[KSPLIT * CELEMS];
__device__ __align__(16)  float g_inv[IN_SZ * 18];

__device__ __forceinline__ float tf32r(float x) {
    uint32_t u;
    asm("cvt.rna.tf32.f32 %0, %1;\n" : "=r"(u) : "f"(x));
    return __uint_as_float(u);
}

// ---------------------------------------------------------------------------
// grid_prep: per-feature reciprocal table
// ---------------------------------------------------------------------------
__global__ void grid_prep_kernel(const float* __restrict__ grid) {
    int i = blockIdx.x * 256 + threadIdx.x;
    if (i >= IN_SZ) return;
    float g[G_SZ];
#pragma unroll
    for (int t = 0; t < G_SZ; t++) g[t] = grid[i * G_SZ + t];
    float* o = g_inv + i * 18;
    int idx = 0;
#pragma unroll
    for (int order = 1; order <= 3; order++) {
#pragma unroll
        for (int j = 0; j < G_SZ; j++) {
            if (j < G_SZ - order) {
                int i2 = (j + order     < G_SZ - 1) ? (j + order)     : (G_SZ - 1);
                int i3 = (j + order + 1 < G_SZ - 1) ? (j + order + 1) : (G_SZ - 1);
                o[idx * 2]     = 1.0f / (g[i2] - g[j] + EPS_F);
                o[idx * 2 + 1] = 1.0f / (g[i3] - g[j + 1] + EPS_F);
                idx++;
            }
        }
    }
}

// basis recursion using precomputed reciprocals
__device__ __forceinline__ void basis5_inv(float xv, const float* g,
                                           const float* inv, float* bas) {
    float diff[G_SZ];
#pragma unroll
    for (int t = 0; t < G_SZ; t++) {
        diff[t] = xv - g[t];
        bas[t] = (diff[t] >= 0.0f && diff[t] < 1.0f) ? 1.0f : 0.0f;
    }
    int idx = 0;
#pragma unroll
    for (int order = 1; order <= 3; order++) {
        float nb[G_SZ];
#pragma unroll
        for (int j = 0; j < G_SZ; j++) nb[j] = bas[j];
#pragma unroll
        for (int j = 0; j < G_SZ; j++) {
            if (j < G_SZ - order) {
                int i3 = (j + order + 1 < G_SZ - 1) ? (j + order + 1) : (G_SZ - 1);
                float t1 = (diff[j] - g[j]) * inv[idx * 2]     * bas[j];
                float t2 = (g[i3] - diff[j]) * inv[idx * 2 + 1] * bas[j + 1];
                nb[j] = t1 + t2;
                idx++;
            }
        }
#pragma unroll
        for (int j = 0; j < G_SZ; j++) bas[j] = nb[j];
    }
}

// ---------------------------------------------------------------------------
// pack_A: tile 16 b x 128 i; thread = (1 feature, 8 b-rows); float2 inv loads
// ---------------------------------------------------------------------------
__global__ __launch_bounds__(256, 4)
void pack_A_kernel(const float* __restrict__ x, const float* __restrict__ grid) {
    extern __shared__ float s[];
    float* sOut = s;             // 12288 floats (48KB)
    const int tid = threadIdx.x;
    const int b0 = blockIdx.x * 16, i0 = blockIdx.y * 128;
    const int ih = tid & 127;
    const int bh = tid >> 7;
    const int i = i0 + ih;

    float g[G_SZ], inv[18];
#pragma unroll
    for (int t = 0; t < G_SZ; t++) g[t] = grid[(size_t)i * G_SZ + t];
    const float2* iv2 = (const float2*)(g_inv + (size_t)i * 18);
#pragma unroll
    for (int t = 0; t < 9; t++) {
        float2 p = iv2[t];
        inv[t * 2] = p.x;
        inv[t * 2 + 1] = p.y;
    }

#pragma unroll
    for (int pb = 0; pb < 8; pb++) {
        const int bl = bh * 8 + pb;
        float xv = x[(size_t)(b0 + bl) * IN_SZ + i];
        float bas[G_SZ], v[KPACK];
        basis5_inv(xv, g, inv, bas);
        v[0] = tf32r(xv);
#pragma unroll
        for (int t = 0; t < G_SZ; t++) v[1 + t] = tf32r(bas[t]);
#pragma unroll
        for (int c = 0; c < KPACK; c++) {
            int kr = ih * KPACK + c;
            int kgl = kr >> 3;
            int chunk = (pb << 2) + (kr & 3);
            int pos = bh + (((kr >> 2) & 1) << 1);
            sOut[kgl * 128 + chunk * 4 + pos] = v[c];
        }
    }
    __syncthreads();

    float4* dst = (float4*)g_Apack +
                  ((size_t)(b0 >> 4) * NKG + (size_t)(i0 * KPACK) / 8) * 32;
    const float4* srcv = (const float4*)sOut;
#pragma unroll
    for (int j = 0; j < 12; j++) dst[tid + j * 256] = srcv[tid + j * 256];
}

// ---------------------------------------------------------------------------
// pack_W: tile 8 o x 256 i per block
// ---------------------------------------------------------------------------
__global__ __launch_bounds__(256, 4)
void pack_W_kernel(const float* __restrict__ bw, const float* __restrict__ sw) {
    extern __shared__ float s[];
    float* sOut = s;             // 12288 floats
    const int tid = threadIdx.x;
    const int o0 = blockIdx.x * 8, i0 = blockIdx.y * 256;

    const int ol = tid >> 5;
    const int il0 = tid & 31;
#pragma unroll
    for (int pi = 0; pi < 8; pi++) {
        int il = il0 + pi * 32;
        size_t oi = (size_t)(o0 + ol) * IN_SZ + i0 + il;
        float v[KPACK];
        v[0] = tf32r(bw[oi]);
#pragma unroll
        for (int t = 0; t < G_SZ; t++) v[1 + t] = tf32r(sw[oi * G_SZ + t]);
#pragma unroll
        for (int c = 0; c < KPACK; c++) {
            int kr = il * KPACK + c;
            int pl = kr >> 4;
            int chunk = ((ol & 7) << 2) + (kr & 3);
            int pos = (kr & 15) >> 2;
            sOut[pl * 128 + chunk * 4 + pos] = v[c];
        }
    }
    __syncthreads();

    float4* dst = (float4*)g_Wpack +
                  ((size_t)(o0 >> 3) * NKGP + (size_t)(i0 * KPACK) / 16) * 32;
    const float4* srcv = (const float4*)sOut;
#pragma unroll
    for (int j = 0; j < 12; j++) dst[tid + j * 256] = srcv[tid + j * 256];
}

// ---------------------------------------------------------------------------
__device__ __forceinline__ uint32_t smem_addr_u32(const void* p) {
    uint32_t a;
    asm("{ .reg .u64 t; cvta.to.shared.u64 t, %1; cvt.u32.u64 %0, t; }"
        : "=r"(a) : "l"(p));
    return a;
}
__device__ __forceinline__ void cpa16(uint32_t dst, const void* src) {
    asm volatile("cp.async.cg.shared.global [%0], [%1], 16;\n" :: "r"(dst), "l"(src));
}
__device__ __forceinline__ void lds128(uint32_t& r0, uint32_t& r1,
                                       uint32_t& r2, uint32_t& r3, uint32_t addr) {
    asm volatile("ld.shared.v4.u32 {%0,%1,%2,%3}, [%4];"
                 : "=r"(r0), "=r"(r1), "=r"(r2), "=r"(r3) : "r"(addr));
}

// ---------------------------------------------------------------------------
// Split-K2 TF32 GEMM: 256x128 tile, BK=64, 2-stage 96KB, 8 warps (4m x 2n,
// 64x64). cp.async prefetch interleaved into ks=0..3 (6 instr/thread/ks)
// so LDGSTS issue-accept stalls don't starve the tensor pipe.
// ---------------------------------------------------------------------------
__global__ __launch_bounds__(256)
void gemm_tf32_kernel() {
    extern __shared__ char smem[];
    const uint32_t sb = smem_addr_u32(smem);
    const int tid = threadIdx.x;
    const int warp = tid >> 5, lane = tid & 31;
    const int gid = lane >> 2, tg = lane & 3;
    const int wm = warp >> 1, wn = warp & 1;
    const uint32_t lane16 = (uint32_t)lane * 16u;
    const int bn = blockIdx.x, bm = blockIdx.y, kz = blockIdx.z;
    const int kbase = kz * KITERS_H;

    const char* Ag = (const char*)g_Apack + (size_t)(bm * 16) * NKG  * 512;
    const char* Wg = (const char*)g_Wpack + (size_t)(bn * 16) * NKGP * 512;

    // chunked prefetch: A p_ in [4c,4c+4), B p_ in [2c,2c+2); 4 chunks cover all
#define LOAD_CHUNK(KT, ST, C)                                                      \
    {                                                                              \
        uint32_t base_ = sb + (uint32_t)(ST) * STAGE_BYTES;                        \
        _Pragma("unroll")                                                          \
        for (int q_ = 0; q_ < 4; q_++) {                                           \
            int p_ = (C) * 4 + q_;                                                 \
            int id_ = tid + p_ * 256;                                              \
            int pan_ = id_ >> 8, kgl_ = (id_ >> 5) & 7, ch_ = id_ & 31;            \
            cpa16(base_ + (uint32_t)(pan_ * 4096 + kgl_ * 512 + ch_ * 16),         \
                  Ag + ((size_t)pan_ * NKG + (size_t)(KT) * 8 + kgl_) * 512        \
                     + ch_ * 16);                                                  \
        }                                                                          \
        _Pragma("unroll")                                                          \
        for (int q_ = 0; q_ < 2; q_++) {                                           \
            int p_ = (C) * 2 + q_;                                                 \
            int id_ = tid + p_ * 256;                                              \
            int pan_ = id_ >> 7, pl_ = (id_ >> 5) & 3, ch_ = id_ & 31;             \
            cpa16(base_ + A_STAGE_BYTES +                                          \
                      (uint32_t)(pan_ * 2048 + pl_ * 512 + ch_ * 16),              \
                  Wg + ((size_t)pan_ * NKGP + (size_t)(KT) * 4 + pl_) * 512        \
                     + ch_ * 16);                                                  \
        }                                                                          \
    }

    float acc[4][8][4];
#pragma unroll
    for (int a = 0; a < 4; a++)
#pragma unroll
        for (int b = 0; b < 8; b++)
#pragma unroll
            for (int c = 0; c < 4; c++) acc[a][b][c] = 0.0f;

    // prologue: full tile 0 load
#pragma unroll
    for (int c = 0; c < 4; c++) LOAD_CHUNK(kbase, 0, c);
    asm volatile("cp.async.commit_group;\n" ::: "memory");

    for (int kt = 0; kt < KITERS_H; kt++) {
        asm volatile("cp.async.wait_group 0;\n" ::: "memory");
        __syncthreads();

        const bool pf = (kt + 1 < KITERS_H);
        const int pfst = (kt + 1) & 1;

        const uint32_t As = sb + (uint32_t)(kt & 1) * STAGE_BYTES;
        const uint32_t Bs = As + A_STAGE_BYTES;

        uint32_t aa[2][4][4];
        uint32_t bp[8][4];

#pragma unroll
        for (int mf = 0; mf < 4; mf++)
            lds128(aa[0][mf][0], aa[0][mf][1], aa[0][mf][2], aa[0][mf][3],
                   As + (uint32_t)(((wm * 4 + mf) * 8 + 0) * 512) + lane16);

#pragma unroll
        for (int ks = 0; ks < 8; ks++) {
            if ((ks & 1) == 0) {
#pragma unroll
                for (int nf = 0; nf < 8; nf++) {
                    uint32_t baddr = Bs +
                        (uint32_t)(((wn * 8 + nf) * 4 + (ks >> 1)) * 512) + lane16;
                    lds128(bp[nf][0], bp[nf][1], bp[nf][2], bp[nf][3], baddr);
                }
            }
            if (ks < 7) {
#pragma unroll
                for (int mf = 0; mf < 4; mf++)
                    lds128(aa[(ks + 1) & 1][mf][0], aa[(ks + 1) & 1][mf][1],
                           aa[(ks + 1) & 1][mf][2], aa[(ks + 1) & 1][mf][3],
                           As + (uint32_t)(((wm * 4 + mf) * 8 + ks + 1) * 512) + lane16);
            }
            // interleaved prefetch of next tile: chunks at ks=0..3, commit at 3
            if (ks < 4 && pf) {
                LOAD_CHUNK(kbase + kt + 1, pfst, ks);
                if (ks == 3)
                    asm volatile("cp.async.commit_group;\n" ::: "memory");
            }

            const int h = (ks & 1) * 2;
            const int cur = ks & 1;
#pragma unroll
            for (int mf = 0; mf < 4; mf++) {
#pragma unroll
                for (int nf = 0; nf < 8; nf++) {
                    asm volatile(
                        "mma.sync.aligned.m16n8k8.row.col.f32.tf32.tf32.f32 "
                        "{%0,%1,%2,%3}, {%4,%5,%6,%7}, {%8,%9}, {%0,%1,%2,%3};\n"
                        : "+f"(acc[mf][nf][0]), "+f"(acc[mf][nf][1]),
                          "+f"(acc[mf][nf][2]), "+f"(acc[mf][nf][3])
                        : "r"(aa[cur][mf][0]), "r"(aa[cur][mf][1]),
                          "r"(aa[cur][mf][2]), "r"(aa[cur][mf][3]),
                          "r"(bp[nf][h]), "r"(bp[nf][h + 1]));
                }
            }
        }
        // no prefetch on the last kt: commit empty group to keep wait math valid
        if (!pf) asm volatile("cp.async.commit_group;\n" ::: "memory");
    }

    float* part = g_part + (size_t)kz * CELEMS;
#pragma unroll
    for (int mf = 0; mf < 4; mf++) {
        int row = bm * BM + wm * 64 + mf * 16 + gid;
#pragma unroll
        for (int nf = 0; nf < 8; nf++) {
            int col = bn * BN + wn * 64 + nf * 8 + tg * 2;
            float2 v0 = make_float2(acc[mf][nf][0], acc[mf][nf][1]);
            float2 v1 = make_float2(acc[mf][nf][2], acc[mf][nf][3]);
            *(float2*)(part + (size_t)row * OUT_SZ + col) = v0;
            *(float2*)(part + (size_t)(row + 8) * OUT_SZ + col) = v1;
        }
    }
#undef LOAD_CHUNK
}

// ---------------------------------------------------------------------------
// reduce: out = part0 + part1 + bias
// ---------------------------------------------------------------------------
__global__ __launch_bounds__(256)
void reduce_kernel(const float* __restrict__ bias, float* __restrict__ out) {
    size_t i = (size_t)blockIdx.x * 256 + threadIdx.x;
    const float4 p0 = ((const float4*)g_part)[i];
    const float4 p1 = ((const float4*)(g_part + CELEMS))[i];
    const int col = (int)((i * 4) & (OUT_SZ - 1));
    const float4 bv = *(const float4*)(bias + col);
    float4 v;
    v.x = p0.x + p1.x + bv.x;
    v.y = p0.y + p1.y + bv.y;
    v.z = p0.z + p1.z + bv.z;
    v.w = p0.w + p1.w + bv.w;
    ((float4*)out)[i] = v;
}

// ---------------------------------------------------------------------------
extern "C" void kernel_launch(void* const* d_in, const int* in_sizes, int n_in,
                              void* d_out, int out_size) {
    const float* x    = (const float*)d_in[0];   // [B, IN]
    const float* bw   = (const float*)d_in[1];   // [OUT, IN]
    const float* bb   = (const float*)d_in[2];   // [OUT]
    const float* sw   = (const float*)d_in[3];   // [OUT, IN, G]
    const float* grid = (const float*)d_in[4];   // [IN, G]
    float* out = (float*)d_out;                  // [B, OUT]

    const int packA_smem = 12288 * 4;
    const int packW_smem = 12288 * 4;
    cudaFuncSetAttribute(pack_A_kernel,
                         cudaFuncAttributeMaxDynamicSharedMemorySize, packA_smem);
    cudaFuncSetAttribute(pack_W_kernel,
                         cudaFuncAttributeMaxDynamicSharedMemorySize, packW_smem);

    grid_prep_kernel<<<(IN_SZ + 255) / 256, 256>>>(grid);
    pack_A_kernel<<<dim3(B_SZ / 16, IN_SZ / 128), 256, packA_smem>>>(x, grid);
    pack_W_kernel<<<dim3(OUT_SZ / 8, IN_SZ / 256), 256, packW_smem>>>(bw, sw);

    const int smem_bytes = NSTAGE * STAGE_BYTES;   // 192 KB
    cudaFuncSetAttribute(gemm_tf32_kernel,
                         cudaFuncAttributeMaxDynamicSharedMemorySize, smem_bytes);
    dim3 g(OUT_SZ / BN, B_SZ / BM, KSPLIT);   // (16, 32, 2) = 1024 CTAs
    gemm_tf32_kernel<<<g, 256, smem_bytes>>>();

    reduce_kernel<<<(int)(CELEMS / 4 / 256), 256>>>(bb, out);
}

// round 16
// speedup vs baseline: 1.0428x; 1.0428x over previous
#include <cuda_runtime.h>
#include <cstdint>

#define B_SZ   8192
#define IN_SZ  2048
#define OUT_SZ 2048
#define G_SZ   5
#define KPACK  6
#define K_SZ   (IN_SZ * KPACK)   // 12288
#define EPS_F  1e-8f

#define BM 128
#define BN 128
#define BK 32
#define KSPLIT 2
#define KITERS_H (K_SZ / BK / KSPLIT)   // 192 per k-slice
#define NSTAGE 2
#define A_STAGE_BYTES (8  * 4 * 512)    // 16 KB
#define B_STAGE_BYTES (16 * 2 * 512)    // 16 KB
#define STAGE_BYTES (A_STAGE_BYTES + B_STAGE_BYTES)   // 32 KB

#define NKG   (K_SZ / 8)          // 1536 k-groups (A)
#define NKGP  (K_SZ / 16)         // 768 kgroup-pairs (B)
#define CELEMS ((size_t)B_SZ * OUT_SZ)

__device__ __align__(128) float g_Apack[(size_t)B_SZ  * K_SZ];
__device__ __align__(128) float g_Wpack[(size_t)OUT_SZ * K_SZ];
__device__ __align__(128) float g_part[KSPLIT * CELEMS];
__device__ __align__(16)  float g_inv[IN_SZ * 18];

__device__ __forceinline__ float tf32r(float x) {
    uint32_t u;
    asm("cvt.rna.tf32.f32 %0, %1;\n" : "=r"(u) : "f"(x));
    return __uint_as_float(u);
}

// ---------------------------------------------------------------------------
// grid_prep: per-feature reciprocal table
// ---------------------------------------------------------------------------
__global__ void grid_prep_kernel(const float* __restrict__ grid) {
    int i = blockIdx.x * 256 + threadIdx.x;
    if (i >= IN_SZ) return;
    float g[G_SZ];
#pragma unroll
    for (int t = 0; t < G_SZ; t++) g[t] = grid[i * G_SZ + t];
    float* o = g_inv + i * 18;
    int idx = 0;
#pragma unroll
    for (int order = 1; order <= 3; order++) {
#pragma unroll
        for (int j = 0; j < G_SZ; j++) {
            if (j < G_SZ - order) {
                int i2 = (j + order     < G_SZ - 1) ? (j + order)     : (G_SZ - 1);
                int i3 = (j + order + 1 < G_SZ - 1) ? (j + order + 1) : (G_SZ - 1);
                o[idx * 2]     = 1.0f / (g[i2] - g[j] + EPS_F);
                o[idx * 2 + 1] = 1.0f / (g[i3] - g[j + 1] + EPS_F);
                idx++;
            }
        }
    }
}

// basis recursion using precomputed reciprocals
__device__ __forceinline__ void basis5_inv(float xv, const float* g,
                                           const float* inv, float* bas) {
    float diff[G_SZ];
#pragma unroll
    for (int t = 0; t < G_SZ; t++) {
        diff[t] = xv - g[t];
        bas[t] = (diff[t] >= 0.0f && diff[t] < 1.0f) ? 1.0f : 0.0f;
    }
    int idx = 0;
#pragma unroll
    for (int order = 1; order <= 3; order++) {
        float nb[G_SZ];
#pragma unroll
        for (int j = 0; j < G_SZ; j++) nb[j] = bas[j];
#pragma unroll
        for (int j = 0; j < G_SZ; j++) {
            if (j < G_SZ - order) {
                int i3 = (j + order + 1 < G_SZ - 1) ? (j + order + 1) : (G_SZ - 1);
                float t1 = (diff[j] - g[j]) * inv[idx * 2]     * bas[j];
                float t2 = (g[i3] - diff[j]) * inv[idx * 2 + 1] * bas[j + 1];
                nb[j] = t1 + t2;
                idx++;
            }
        }
#pragma unroll
        for (int j = 0; j < G_SZ; j++) bas[j] = nb[j];
    }
}

// ---------------------------------------------------------------------------
// pack_A: tile 16 b x 128 i; thread = (1 feature, 8 b-rows); float2 inv loads
// ---------------------------------------------------------------------------
__global__ __launch_bounds__(256, 4)
void pack_A_kernel(const float* __restrict__ x, const float* __restrict__ grid) {
    extern __shared__ float s[];
    float* sOut = s;             // 12288 floats (48KB)
    const int tid = threadIdx.x;
    const int b0 = blockIdx.x * 16, i0 = blockIdx.y * 128;
    const int ih = tid & 127;
    const int bh = tid >> 7;
    const int i = i0 + ih;

    float g[G_SZ], inv[18];
#pragma unroll
    for (int t = 0; t < G_SZ; t++) g[t] = grid[(size_t)i * G_SZ + t];
    const float2* iv2 = (const float2*)(g_inv + (size_t)i * 18);
#pragma unroll
    for (int t = 0; t < 9; t++) {
        float2 p = iv2[t];
        inv[t * 2] = p.x;
        inv[t * 2 + 1] = p.y;
    }

#pragma unroll
    for (int pb = 0; pb < 8; pb++) {
        const int bl = bh * 8 + pb;
        float xv = x[(size_t)(b0 + bl) * IN_SZ + i];
        float bas[G_SZ], v[KPACK];
        basis5_inv(xv, g, inv, bas);
        v[0] = tf32r(xv);
#pragma unroll
        for (int t = 0; t < G_SZ; t++) v[1 + t] = tf32r(bas[t]);
#pragma unroll
        for (int c = 0; c < KPACK; c++) {
            int kr = ih * KPACK + c;
            int kgl = kr >> 3;
            int chunk = (pb << 2) + (kr & 3);
            int pos = bh + (((kr >> 2) & 1) << 1);
            sOut[kgl * 128 + chunk * 4 + pos] = v[c];
        }
    }
    __syncthreads();

    float4* dst = (float4*)g_Apack +
                  ((size_t)(b0 >> 4) * NKG + (size_t)(i0 * KPACK) / 8) * 32;
    const float4* srcv = (const float4*)sOut;
#pragma unroll
    for (int j = 0; j < 12; j++) dst[tid + j * 256] = srcv[tid + j * 256];
}

// ---------------------------------------------------------------------------
// pack_W: tile 8 o x 256 i per block
// ---------------------------------------------------------------------------
__global__ __launch_bounds__(256, 4)
void pack_W_kernel(const float* __restrict__ bw, const float* __restrict__ sw) {
    extern __shared__ float s[];
    float* sOut = s;             // 12288 floats
    const int tid = threadIdx.x;
    const int o0 = blockIdx.x * 8, i0 = blockIdx.y * 256;

    const int ol = tid >> 5;
    const int il0 = tid & 31;
#pragma unroll
    for (int pi = 0; pi < 8; pi++) {
        int il = il0 + pi * 32;
        size_t oi = (size_t)(o0 + ol) * IN_SZ + i0 + il;
        float v[KPACK];
        v[0] = tf32r(bw[oi]);
#pragma unroll
        for (int t = 0; t < G_SZ; t++) v[1 + t] = tf32r(sw[oi * G_SZ + t]);
#pragma unroll
        for (int c = 0; c < KPACK; c++) {
            int kr = il * KPACK + c;
            int pl = kr >> 4;
            int chunk = ((ol & 7) << 2) + (kr & 3);
            int pos = (kr & 15) >> 2;
            sOut[pl * 128 + chunk * 4 + pos] = v[c];
        }
    }
    __syncthreads();

    float4* dst = (float4*)g_Wpack +
                  ((size_t)(o0 >> 3) * NKGP + (size_t)(i0 * KPACK) / 16) * 32;
    const float4* srcv = (const float4*)sOut;
#pragma unroll
    for (int j = 0; j < 12; j++) dst[tid + j * 256] = srcv[tid + j * 256];
}

// ---------------------------------------------------------------------------
__device__ __forceinline__ uint32_t smem_addr_u32(const void* p) {
    uint32_t a;
    asm("{ .reg .u64 t; cvta.to.shared.u64 t, %1; cvt.u32.u64 %0, t; }"
        : "=r"(a) : "l"(p));
    return a;
}
__device__ __forceinline__ void cpa16(uint32_t dst, const void* src) {
    asm volatile("cp.async.cg.shared.global [%0], [%1], 16;\n" :: "r"(dst), "l"(src));
}
__device__ __forceinline__ void lds128(uint32_t& r0, uint32_t& r1,
                                       uint32_t& r2, uint32_t& r3, uint32_t addr) {
    asm volatile("ld.shared.v4.u32 {%0,%1,%2,%3}, [%4];"
                 : "=r"(r0), "=r"(r1), "=r"(r2), "=r"(r3) : "r"(addr));
}

// ---------------------------------------------------------------------------
// Split-K2 TF32 GEMM: 128x128 tile, BK=32, 128 threads (4 warps, 2m x 2n of
// 64x64), NSTAGE=2 (64KB), 2 CTAs/SM -> barrier windows overlap across CTAs.
// Full 256-reg/thread budget at occupancy 2: no spill.
// ---------------------------------------------------------------------------
__global__ __launch_bounds__(128, 2)
void gemm_tf32_kernel() {
    extern __shared__ char smem[];
    const uint32_t sb = smem_addr_u32(smem);
    const int tid = threadIdx.x;
    const int warp = tid >> 5, lane = tid & 31;
    const int gid = lane >> 2, tg = lane & 3;
    const int wm = warp & 1, wn = warp >> 1;     // 2 m-warps x 2 n-warps, 64x64
    const uint32_t lane16 = (uint32_t)lane * 16u;
    const int bn = blockIdx.x, bm = blockIdx.y, kz = blockIdx.z;
    const int kbase = kz * KITERS_H;

    const char* Ag = (const char*)g_Apack + (size_t)(bm * 8)  * NKG  * 512;
    const char* Wg = (const char*)g_Wpack + (size_t)(bn * 16) * NKGP * 512;

#define LOADST(KT, ST)                                                             \
    {                                                                              \
        uint32_t base_ = sb + (uint32_t)(ST) * STAGE_BYTES;                        \
        _Pragma("unroll")                                                          \
        for (int p_ = 0; p_ < 8; p_++) {   /* A: 1024 chunks, 128 thr */           \
            int id_ = tid + p_ * 128;                                              \
            int pan_ = id_ >> 7, kgl_ = (id_ >> 5) & 3, ch_ = id_ & 31;            \
            cpa16(base_ + (uint32_t)(pan_ * 2048 + kgl_ * 512 + ch_ * 16),         \
                  Ag + ((size_t)pan_ * NKG + (size_t)(KT) * 4 + kgl_) * 512        \
                     + ch_ * 16);                                                  \
        }                                                                          \
        _Pragma("unroll")                                                          \
        for (int p_ = 0; p_ < 8; p_++) {   /* B: 1024 chunks */                    \
            int id_ = tid + p_ * 128;                                              \
            int pan_ = id_ >> 6, pl_ = (id_ >> 5) & 1, ch_ = id_ & 31;             \
            cpa16(base_ + A_STAGE_BYTES +                                          \
                      (uint32_t)(pan_ * 1024 + pl_ * 512 + ch_ * 16),              \
                  Wg + ((size_t)pan_ * NKGP + (size_t)(KT) * 2 + pl_) * 512        \
                     + ch_ * 16);                                                  \
        }                                                                          \
        asm volatile("cp.async.commit_group;\n" ::: "memory");                     \
    }

    float acc[4][8][4];
#pragma unroll
    for (int a = 0; a < 4; a++)
#pragma unroll
        for (int b = 0; b < 8; b++)
#pragma unroll
            for (int c = 0; c < 4; c++) acc[a][b][c] = 0.0f;

    LOADST(kbase, 0);                          // prologue

    for (int kt = 0; kt < KITERS_H; kt++) {
        asm volatile("cp.async.wait_group 0;\n" ::: "memory");
        __syncthreads();

        if (kt + 1 < KITERS_H) LOADST(kbase + kt + 1, (kt + 1) & 1);

        const uint32_t As = sb + (uint32_t)(kt & 1) * STAGE_BYTES;
        const uint32_t Bs = As + A_STAGE_BYTES;

        uint32_t aa[2][4][4];
        uint32_t bp[8][4];

        // preload A fragments for ks=0
#pragma unroll
        for (int mf = 0; mf < 4; mf++)
            lds128(aa[0][mf][0], aa[0][mf][1], aa[0][mf][2], aa[0][mf][3],
                   As + (uint32_t)(((wm * 4 + mf) * 4 + 0) * 512) + lane16);

#pragma unroll
        for (int ks = 0; ks < 4; ks++) {
            if ((ks & 1) == 0) {               // B pair for ks, ks+1
#pragma unroll
                for (int nf = 0; nf < 8; nf++) {
                    uint32_t baddr = Bs +
                        (uint32_t)(((wn * 8 + nf) * 2 + (ks >> 1)) * 512) + lane16;
                    lds128(bp[nf][0], bp[nf][1], bp[nf][2], bp[nf][3], baddr);
                }
            }
            if (ks < 3) {                      // prefetch next ks's A fragments
#pragma unroll
                for (int mf = 0; mf < 4; mf++)
                    lds128(aa[(ks + 1) & 1][mf][0], aa[(ks + 1) & 1][mf][1],
                           aa[(ks + 1) & 1][mf][2], aa[(ks + 1) & 1][mf][3],
                           As + (uint32_t)(((wm * 4 + mf) * 4 + ks + 1) * 512) + lane16);
            }
            const int h = (ks & 1) * 2;
            const int cur = ks & 1;
#pragma unroll
            for (int mf = 0; mf < 4; mf++) {
#pragma unroll
                for (int nf = 0; nf < 8; nf++) {
                    asm volatile(
                        "mma.sync.aligned.m16n8k8.row.col.f32.tf32.tf32.f32 "
                        "{%0,%1,%2,%3}, {%4,%5,%6,%7}, {%8,%9}, {%0,%1,%2,%3};\n"
                        : "+f"(acc[mf][nf][0]), "+f"(acc[mf][nf][1]),
                          "+f"(acc[mf][nf][2]), "+f"(acc[mf][nf][3])
                        : "r"(aa[cur][mf][0]), "r"(aa[cur][mf][1]),
                          "r"(aa[cur][mf][2]), "r"(aa[cur][mf][3]),
                          "r"(bp[nf][h]), "r"(bp[nf][h + 1]));
                }
            }
        }
    }

    float* part = g_part + (size_t)kz * CELEMS;
#pragma unroll
    for (int mf = 0; mf < 4; mf++) {
        int row = bm * BM + wm * 64 + mf * 16 + gid;
#pragma unroll
        for (int nf = 0; nf < 8; nf++) {
            int col = bn * BN + wn * 64 + nf * 8 + tg * 2;
            float2 v0 = make_float2(acc[mf][nf][0], acc[mf][nf][1]);
            float2 v1 = make_float2(acc[mf][nf][2], acc[mf][nf][3]);
            *(float2*)(part + (size_t)row * OUT_SZ + col) = v0;
            *(float2*)(part + (size_t)(row + 8) * OUT_SZ + col) = v1;
        }
    }
#undef LOADST
}

// ---------------------------------------------------------------------------
// reduce: out = part0 + part1 + bias
// ---------------------------------------------------------------------------
__global__ __launch_bounds__(256)
void reduce_kernel(const float* __restrict__ bias, float* __restrict__ out) {
    size_t i = (size_t)blockIdx.x * 256 + threadIdx.x;
    const float4 p0 = ((const float4*)g_part)[i];
    const float4 p1 = ((const float4*)(g_part + CELEMS))[i];
    const int col = (int)((i * 4) & (OUT_SZ - 1));
    const float4 bv = *(const float4*)(bias + col);
    float4 v;
    v.x = p0.x + p1.x + bv.x;
    v.y = p0.y + p1.y + bv.y;
    v.z = p0.z + p1.z + bv.z;
    v.w = p0.w + p1.w + bv.w;
    ((float4*)out)[i] = v;
}

// ---------------------------------------------------------------------------
extern "C" void kernel_launch(void* const* d_in, const int* in_sizes, int n_in,
                              void* d_out, int out_size) {
    const float* x    = (const float*)d_in[0];   // [B, IN]
    const float* bw   = (const float*)d_in[1];   // [OUT, IN]
    const float* bb   = (const float*)d_in[2];   // [OUT]
    const float* sw   = (const float*)d_in[3];   // [OUT, IN, G]
    const float* grid = (const float*)d_in[4];   // [IN, G]
    float* out = (float*)d_out;                  // [B, OUT]

    const int packA_smem = 12288 * 4;
    const int packW_smem = 12288 * 4;
    cudaFuncSetAttribute(pack_A_kernel,
                         cudaFuncAttributeMaxDynamicSharedMemorySize, packA_smem);
    cudaFuncSetAttribute(pack_W_kernel,
                         cudaFuncAttributeMaxDynamicSharedMemorySize, packW_smem);

    grid_prep_kernel<<<(IN_SZ + 255) / 256, 256>>>(grid);
    pack_A_kernel<<<dim3(B_SZ / 16, IN_SZ / 128), 256, packA_smem>>>(x, grid);
    pack_W_kernel<<<dim3(OUT_SZ / 8, IN_SZ / 256), 256, packW_smem>>>(bw, sw);

    const int smem_bytes = NSTAGE * STAGE_BYTES;   // 64 KB per CTA
    cudaFuncSetAttribute(gemm_tf32_kernel,
                         cudaFuncAttributeMaxDynamicSharedMemorySize, smem_bytes);
    dim3 g(OUT_SZ / BN, B_SZ / BM, KSPLIT);   // (16, 64, 2) = 2048 CTAs
    gemm_tf32_kernel<<<g, 128, smem_bytes>>>();

    reduce_kernel<<<(int)(CELEMS / 4 / 256), 256>>>(bb, out);
}